// round 9
// baseline (speedup 1.0000x reference)
#include <cuda_runtime.h>
#include <math.h>
#include <stdint.h>

#define CC 10

static const int BLOCK = 256;
static const int GRID  = 1184;
static const int WPB   = 8;
static const int NWARPS = GRID * WPB;
static const int NSLAB = 3;

// Per-slab, per-block partials: 0..9 sum p, 10..19 sum p^2, 20..29 sum v, 30 sum lse
__device__ double g_partials[NSLAB][GRID][32];

// ---------------------------------------------------------------------------
__device__ __forceinline__ uint32_t smem_u32(const void* p) {
    uint32_t a;
    asm("{ .reg .u64 t; cvta.to.shared.u64 t, %1; cvt.u32.u64 %0, t; }"
        : "=r"(a) : "l"(p));
    return a;
}
__device__ __forceinline__ void cp16(uint32_t s, const void* g) {
    asm volatile("cp.async.cg.shared.global [%0], [%1], 16;" :: "r"(s), "l"(g));
}
#define CP_COMMIT() asm volatile("cp.async.commit_group;")
#define CP_WAIT1()  asm volatile("cp.async.wait_group 1;")

// ---------------------------------------------------------------------------
// Stats over tile range [t0, t1) (tiles of 64 rows). Slab selects the output
// partial slab. doTail!=0 also handles rows [nT*64, n).
// ---------------------------------------------------------------------------
__global__ __launch_bounds__(256) void ed_stats(const float* __restrict__ x,
                                                int t0, int t1, int slab,
                                                int n, int doTail) {
    __shared__ float4 stage[WPB][2][160];

    const int lane = threadIdx.x & 31;
    const int w    = threadIdx.x >> 5;
    const int gw   = blockIdx.x * WPB + w;

    float ap [CC], ap2[CC], sv[CC];
    float sM = 0.f;
#pragma unroll
    for (int i = 0; i < CC; i++) { ap[i] = 0.f; ap2[i] = 0.f; sv[i] = 0.f; }

    const float4* __restrict__ x4 = reinterpret_cast<const float4*>(x);

    const uint32_t sb0 = smem_u32(&stage[w][0][0]);
    const uint32_t sb1 = smem_u32(&stage[w][1][0]);

    int t = t0 + gw;
    if (t < t1) {
        const float4* src = x4 + (size_t)t * 160;
#pragma unroll
        for (int j = 0; j < 5; j++)
            cp16(sb0 + (uint32_t)(lane + j * 32) * 16u, src + lane + j * 32);
    }
    CP_COMMIT();

    int cur = 0;
    for (; t < t1; t += NWARPS) {
        const int t2 = t + NWARPS;
        const uint32_t sbn = cur ? sb0 : sb1;
        if (t2 < t1) {
            const float4* src = x4 + (size_t)t2 * 160;
#pragma unroll
            for (int j = 0; j < 5; j++)
                cp16(sbn + (uint32_t)(lane + j * 32) * 16u, src + lane + j * 32);
        }
        CP_COMMIT();
        CP_WAIT1();
        __syncwarp();

        const float4* b = &stage[w][cur][0];
        float4 q0 = b[lane * 5    ];
        float4 q1 = b[lane * 5 + 1];
        float4 q2 = b[lane * 5 + 2];
        float4 q3 = b[lane * 5 + 3];
        float4 q4 = b[lane * 5 + 4];

        float v0[CC] = { q0.x, q0.y, q0.z, q0.w, q1.x, q1.y, q1.z, q1.w, q2.x, q2.y };
        float v1[CC] = { q2.z, q2.w, q3.x, q3.y, q3.z, q3.w, q4.x, q4.y, q4.z, q4.w };

        // Interleaved dual-row softmax: 20 independent MUFU exps, pairwise
        // tree sums, both rcp/log chains overlapped.
        float e0[CC], e1[CC];
#pragma unroll
        for (int i = 0; i < CC; i++) { e0[i] = __expf(v0[i]); e1[i] = __expf(v1[i]); }

        float s0a = e0[0]+e0[1], s0b = e0[2]+e0[3], s0c = e0[4]+e0[5],
              s0d = e0[6]+e0[7], s0e = e0[8]+e0[9];
        float s1a = e1[0]+e1[1], s1b = e1[2]+e1[3], s1c = e1[4]+e1[5],
              s1d = e1[6]+e1[7], s1e = e1[8]+e1[9];
        float s0 = (s0a+s0b) + (s0c+s0d) + s0e;
        float s1 = (s1a+s1b) + (s1c+s1d) + s1e;

        float inv0 = __fdividef(1.f, s0);
        float inv1 = __fdividef(1.f, s1);
        sM += __logf(s0);
        sM += __logf(s1);

#pragma unroll
        for (int i = 0; i < CC; i++) {
            float p0 = e0[i] * inv0;
            float p1 = e1[i] * inv1;
            ap [i] += p0 + p1;
            ap2[i]  = fmaf(p0, p0, ap2[i]);
            ap2[i]  = fmaf(p1, p1, ap2[i]);
            sv [i] += v0[i] + v1[i];
        }

        __syncwarp();
        cur ^= 1;
    }

    // tail rows (only in last slab; none for n % 64 == 0)
    if (doTail) {
        const int nT = n >> 6;
        for (int r0 = (nT << 6) + blockIdx.x * blockDim.x + threadIdx.x; r0 < n;
             r0 += gridDim.x * blockDim.x) {
            const float2* row = reinterpret_cast<const float2*>(x) + r0 * 5;
            float v[CC];
#pragma unroll
            for (int j = 0; j < 5; j++) { float2 t2 = row[j]; v[2*j] = t2.x; v[2*j+1] = t2.y; }
            float e[CC], s = 0.f;
#pragma unroll
            for (int i = 0; i < CC; i++) { e[i] = __expf(v[i]); s += e[i]; }
            float inv = __fdividef(1.f, s);
            sM += __logf(s);
#pragma unroll
            for (int i = 0; i < CC; i++) {
                float p = e[i] * inv;
                ap[i] += p; ap2[i] = fmaf(p, p, ap2[i]); sv[i] += v[i];
            }
        }
    }

    // ---- block reduction: 31 stats -> double partials ----
#pragma unroll
    for (int i = 0; i < CC; i++) {
#pragma unroll
        for (int o = 16; o > 0; o >>= 1) {
            ap [i] += __shfl_down_sync(0xffffffffu, ap [i], o);
            ap2[i] += __shfl_down_sync(0xffffffffu, ap2[i], o);
            sv [i] += __shfl_down_sync(0xffffffffu, sv [i], o);
        }
    }
#pragma unroll
    for (int o = 16; o > 0; o >>= 1) sM += __shfl_down_sync(0xffffffffu, sM, o);

    __shared__ float sh[31][WPB];
    if (lane == 0) {
#pragma unroll
        for (int i = 0; i < CC; i++) {
            sh[i     ][w] = ap [i];
            sh[10 + i][w] = ap2[i];
            sh[20 + i][w] = sv [i];
        }
        sh[30][w] = sM;
    }
    __syncthreads();
    if (threadIdx.x < 31) {
        double s2 = 0.0;
#pragma unroll
        for (int w2 = 0; w2 < WPB; w2++) s2 += (double)sh[threadIdx.x][w2];
        g_partials[slab][blockIdx.x][threadIdx.x] = s2;
    }
}

// ---------------------------------------------------------------------------
// Fused branchless digamma + trigamma (shift to x+6 + asymptotic series).
// ---------------------------------------------------------------------------
__device__ __forceinline__ void psi01(float x, float& dg, float& tg) {
    float s0 = 0.f, s1 = 0.f;
#pragma unroll
    for (int k = 0; k < 6; k++) {
        float r = __fdividef(1.f, x + (float)k);
        s0 += r;
        s1  = fmaf(r, r, s1);
    }
    float y  = x + 6.f;
    float r  = __fdividef(1.f, y);
    float r2 = r * r;
    dg = __logf(y) - 0.5f * r
       - r2 * (0.0833333333f - r2 * (0.0083333333f - r2 * 0.0039682540f))
       - s0;
    tg = r + 0.5f * r2
       + r * r2 * (0.1666666667f - r2 * (0.0333333333f - r2 * 0.0238095238f))
       + s1;
}

__device__ __forceinline__ void allred2_16(float& v1, float& v2) {
#pragma unroll
    for (int o = 8; o > 0; o >>= 1) {
        v1 += __shfl_xor_sync(0xffffffffu, v1, o);
        v2 += __shfl_xor_sync(0xffffffffu, v2, o);
    }
}
__device__ __forceinline__ float allred1_16(float v) {
#pragma unroll
    for (int o = 8; o > 0; o >>= 1) v += __shfl_xor_sync(0xffffffffu, v, o);
    return v;
}

// ---------------------------------------------------------------------------
// Solve: reduce partials (warp per stat over all slabs) + Newton, 10 iters.
// ---------------------------------------------------------------------------
__global__ __launch_bounds__(1024) void ed_solve(float* __restrict__ out, int n) {
    __shared__ double st[32];
    const int tid  = threadIdx.x;
    const int w    = tid >> 5;
    const int lane = tid & 31;

    if (w < 31) {
        double s = 0.0;
        const double* base = &g_partials[0][0][0];
        for (int b = lane; b < NSLAB * GRID; b += 32) s += base[b * 32 + w];
#pragma unroll
        for (int o = 16; o > 0; o >>= 1) s += __shfl_down_sync(0xffffffffu, s, o);
        if (lane == 0) st[w] = s;
    }
    __syncthreads();

    if (w == 0) {
        const bool  act = (lane < CC);
        const double dn = (double)n;

        float m1  = act ? (float)(st[lane]      / dn) : 0.f;
        float m2  = act ? (float)(st[10 + lane] / dn) : 0.f;
        float lpa = act ? (float)((st[20 + lane] - st[30]) / dn) : 0.f;

        float ratio = act ? (m1 - m2) / (m2 - m1 * m1) : 0.f;
        float rmean = allred1_16(ratio) * 0.1f;
        float a     = act ? m1 * rmean : 0.f;
        float asum  = allred1_16(a);
        if (!act) { a = 1.0f; asum = 20.0f; }

#pragma unroll 1
        for (int k = 0; k < 10; k++) {
            float dga, tga, dgs, tgs;
            psi01(a,    dga, tga);
            psi01(asum, dgs, tgs);
            float g    = dgs - dga + lpa;
            float qinv = __fdividef(-1.f, tga);
            float num  = act ? g * qinv : 0.f;
            float qs   = act ? qinv     : 0.f;
            allred2_16(num, qs);
            float zinv = __fdividef(1.f, tgs);
            float b    = num / (zinv + qs);
            a    = act ? a - (g - b) * qinv : 1.0f;
            asum = act ? asum - (num - b * qs) : 20.0f;
        }
        if (act) out[lane] = a;
    }
}

// ---------------------------------------------------------------------------
extern "C" void kernel_launch(void* const* d_in, const int* in_sizes, int n_in,
                              void* d_out, int out_size) {
    const float* x = (const float*)d_in[0];
    const int n  = in_sizes[0] / CC;   // 2,000,000 rows
    const int nT = n >> 6;             // 31250 tiles
    const int c1 = nT / 3, c2 = 2 * nT / 3;
    ed_stats<<<GRID, BLOCK>>>(x, 0,  c1, 0, n, 0);
    ed_stats<<<GRID, BLOCK>>>(x, c1, c2, 1, n, 0);
    ed_stats<<<GRID, BLOCK>>>(x, c2, nT, 2, n, 1);
    ed_solve<<<1, 1024>>>((float*)d_out, n);
}

// round 10
// speedup vs baseline: 3.8622x; 3.8622x over previous
#include <cuda_runtime.h>
#include <math.h>
#include <stdint.h>

#define CC 10

static const int BLOCK = 256;
static const int GRID  = 296;      // 2 blocks per SM: amortize launch/drain floor
static const int WPB   = 8;
static const int NWARPS = GRID * WPB;   // 2368 warps, ~13.2 tiles each

// Per-block partials: 0..9 sum p, 10..19 sum p^2, 20..29 sum v, 30 sum logsumexp
__device__ double g_partials[GRID][32];

// ---------------------------------------------------------------------------
__device__ __forceinline__ uint32_t smem_u32(const void* p) {
    uint32_t a;
    asm("{ .reg .u64 t; cvta.to.shared.u64 t, %1; cvt.u32.u64 %0, t; }"
        : "=r"(a) : "l"(p));
    return a;
}
__device__ __forceinline__ void cp16(uint32_t s, const void* g) {
    asm volatile("cp.async.cg.shared.global [%0], [%1], 16;" :: "r"(s), "l"(g));
}
#define CP_COMMIT() asm volatile("cp.async.commit_group;")
#define CP_WAIT1()  asm volatile("cp.async.wait_group 1;")

// ---------------------------------------------------------------------------
// Kernel 1: stats, cp.async double-buffered warp staging, 64-row tiles.
// ---------------------------------------------------------------------------
__global__ __launch_bounds__(256) void ed_stats(const float* __restrict__ x, int n) {
    __shared__ float4 stage[WPB][2][160];

    const int lane = threadIdx.x & 31;
    const int w    = threadIdx.x >> 5;
    const int gw   = blockIdx.x * WPB + w;

    float ap [CC], ap2[CC], sv[CC];
    float sM = 0.f;
#pragma unroll
    for (int i = 0; i < CC; i++) { ap[i] = 0.f; ap2[i] = 0.f; sv[i] = 0.f; }

    const float4* __restrict__ x4 = reinterpret_cast<const float4*>(x);
    const int nT = n >> 6;

    const uint32_t sb0 = smem_u32(&stage[w][0][0]);
    const uint32_t sb1 = smem_u32(&stage[w][1][0]);

    int t = gw;
    if (t < nT) {
        const float4* src = x4 + (size_t)t * 160;
#pragma unroll
        for (int j = 0; j < 5; j++)
            cp16(sb0 + (uint32_t)(lane + j * 32) * 16u, src + lane + j * 32);
    }
    CP_COMMIT();

    int cur = 0;
    for (; t < nT; t += NWARPS) {
        const int t2 = t + NWARPS;
        const uint32_t sbn = cur ? sb0 : sb1;
        if (t2 < nT) {
            const float4* src = x4 + (size_t)t2 * 160;
#pragma unroll
            for (int j = 0; j < 5; j++)
                cp16(sbn + (uint32_t)(lane + j * 32) * 16u, src + lane + j * 32);
        }
        CP_COMMIT();
        CP_WAIT1();
        __syncwarp();

        const float4* b = &stage[w][cur][0];
        float4 q0 = b[lane * 5    ];
        float4 q1 = b[lane * 5 + 1];
        float4 q2 = b[lane * 5 + 2];
        float4 q3 = b[lane * 5 + 3];
        float4 q4 = b[lane * 5 + 4];

        float v0[CC] = { q0.x, q0.y, q0.z, q0.w, q1.x, q1.y, q1.z, q1.w, q2.x, q2.y };
        float v1[CC] = { q2.z, q2.w, q3.x, q3.y, q3.z, q3.w, q4.x, q4.y, q4.z, q4.w };

        // Interleaved dual-row softmax: 20 independent MUFUs, pairwise sums.
        float e0[CC], e1[CC];
#pragma unroll
        for (int i = 0; i < CC; i++) { e0[i] = __expf(v0[i]); e1[i] = __expf(v1[i]); }

        float s0 = ((e0[0]+e0[1]) + (e0[2]+e0[3])) + ((e0[4]+e0[5]) + (e0[6]+e0[7])) + (e0[8]+e0[9]);
        float s1 = ((e1[0]+e1[1]) + (e1[2]+e1[3])) + ((e1[4]+e1[5]) + (e1[6]+e1[7])) + (e1[8]+e1[9]);

        float inv0 = __fdividef(1.f, s0);
        float inv1 = __fdividef(1.f, s1);
        sM += __logf(s0);
        sM += __logf(s1);

#pragma unroll
        for (int i = 0; i < CC; i++) {
            float p0 = e0[i] * inv0;
            float p1 = e1[i] * inv1;
            ap [i] += p0 + p1;
            ap2[i]  = fmaf(p0, p0, ap2[i]);
            ap2[i]  = fmaf(p1, p1, ap2[i]);
            sv [i] += v0[i] + v1[i];
        }

        __syncwarp();
        cur ^= 1;
    }

    // tail rows (none for n % 64 == 0, kept for generality)
    for (int r0 = (nT << 6) + blockIdx.x * blockDim.x + threadIdx.x; r0 < n;
         r0 += gridDim.x * blockDim.x) {
        const float2* row = reinterpret_cast<const float2*>(x) + r0 * 5;
        float v[CC];
#pragma unroll
        for (int j = 0; j < 5; j++) { float2 t2 = row[j]; v[2*j] = t2.x; v[2*j+1] = t2.y; }
        float e[CC], s = 0.f;
#pragma unroll
        for (int i = 0; i < CC; i++) { e[i] = __expf(v[i]); s += e[i]; }
        float inv = __fdividef(1.f, s);
        sM += __logf(s);
#pragma unroll
        for (int i = 0; i < CC; i++) {
            float p = e[i] * inv;
            ap[i] += p; ap2[i] = fmaf(p, p, ap2[i]); sv[i] += v[i];
        }
    }

    // ---- block reduction: 31 stats -> double partials ----
#pragma unroll
    for (int i = 0; i < CC; i++) {
#pragma unroll
        for (int o = 16; o > 0; o >>= 1) {
            ap [i] += __shfl_down_sync(0xffffffffu, ap [i], o);
            ap2[i] += __shfl_down_sync(0xffffffffu, ap2[i], o);
            sv [i] += __shfl_down_sync(0xffffffffu, sv [i], o);
        }
    }
#pragma unroll
    for (int o = 16; o > 0; o >>= 1) sM += __shfl_down_sync(0xffffffffu, sM, o);

    __shared__ float sh[31][WPB];
    if (lane == 0) {
#pragma unroll
        for (int i = 0; i < CC; i++) {
            sh[i     ][w] = ap [i];
            sh[10 + i][w] = ap2[i];
            sh[20 + i][w] = sv [i];
        }
        sh[30][w] = sM;
    }
    __syncthreads();
    if (threadIdx.x < 31) {
        double s2 = 0.0;
#pragma unroll
        for (int w2 = 0; w2 < WPB; w2++) s2 += (double)sh[threadIdx.x][w2];
        g_partials[blockIdx.x][threadIdx.x] = s2;
    }
}

// ---------------------------------------------------------------------------
// Fused branchless digamma + trigamma (shift to x+6 + asymptotic series).
// ---------------------------------------------------------------------------
__device__ __forceinline__ void psi01(float x, float& dg, float& tg) {
    float s0 = 0.f, s1 = 0.f;
#pragma unroll
    for (int k = 0; k < 6; k++) {
        float r = __fdividef(1.f, x + (float)k);
        s0 += r;
        s1  = fmaf(r, r, s1);
    }
    float y  = x + 6.f;
    float r  = __fdividef(1.f, y);
    float r2 = r * r;
    dg = __logf(y) - 0.5f * r
       - r2 * (0.0833333333f - r2 * (0.0083333333f - r2 * 0.0039682540f))
       - s0;
    tg = r + 0.5f * r2
       + r * r2 * (0.1666666667f - r2 * (0.0333333333f - r2 * 0.0238095238f))
       + s1;
}

__device__ __forceinline__ void allred2_16(float& v1, float& v2) {
#pragma unroll
    for (int o = 8; o > 0; o >>= 1) {
        v1 += __shfl_xor_sync(0xffffffffu, v1, o);
        v2 += __shfl_xor_sync(0xffffffffu, v2, o);
    }
}
__device__ __forceinline__ float allred1_16(float v) {
#pragma unroll
    for (int o = 8; o > 0; o >>= 1) v += __shfl_xor_sync(0xffffffffu, v, o);
    return v;
}

// ---------------------------------------------------------------------------
// Kernel 2: reduce 296x32 partials (8 threads per stat) + Newton, 10 iters.
// ---------------------------------------------------------------------------
__global__ __launch_bounds__(256) void ed_solve(float* __restrict__ out, int n) {
    __shared__ double st[32];
    const int tid = threadIdx.x;

    {
        const int stat = tid >> 3, j = tid & 7;   // 32 stats x 8 threads
        double s = 0.0;
#pragma unroll 4
        for (int b = j; b < GRID; b += 8) s += g_partials[b][stat];
        s += __shfl_down_sync(0xffffffffu, s, 4, 8);
        s += __shfl_down_sync(0xffffffffu, s, 2, 8);
        s += __shfl_down_sync(0xffffffffu, s, 1, 8);
        if (j == 0) st[stat] = s;
    }
    __syncthreads();

    if (tid < 32) {
        const int  lane = tid;
        const bool act  = (lane < CC);
        const double dn = (double)n;

        float m1  = act ? (float)(st[lane]      / dn) : 0.f;
        float m2  = act ? (float)(st[10 + lane] / dn) : 0.f;
        float lpa = act ? (float)((st[20 + lane] - st[30]) / dn) : 0.f;

        float ratio = act ? (m1 - m2) / (m2 - m1 * m1) : 0.f;
        float rmean = allred1_16(ratio) * 0.1f;
        float a     = act ? m1 * rmean : 0.f;
        float asum  = allred1_16(a);
        if (!act) { a = 1.0f; asum = 20.0f; }

#pragma unroll 1
        for (int k = 0; k < 10; k++) {
            float dga, tga, dgs, tgs;
            psi01(a,    dga, tga);
            psi01(asum, dgs, tgs);
            float g    = dgs - dga + lpa;
            float qinv = __fdividef(-1.f, tga);
            float num  = act ? g * qinv : 0.f;
            float qs   = act ? qinv     : 0.f;
            allred2_16(num, qs);
            float zinv = __fdividef(1.f, tgs);
            float b    = num / (zinv + qs);
            a    = act ? a - (g - b) * qinv : 1.0f;
            asum = act ? asum - (num - b * qs) : 20.0f;
        }
        if (act) out[lane] = a;
    }
}

// ---------------------------------------------------------------------------
extern "C" void kernel_launch(void* const* d_in, const int* in_sizes, int n_in,
                              void* d_out, int out_size) {
    const float* x = (const float*)d_in[0];
    const int n = in_sizes[0] / CC;   // 2,000,000 rows
    ed_stats<<<GRID, BLOCK>>>(x, n);
    ed_solve<<<1, 256>>>((float*)d_out, n);
}

// round 11
// speedup vs baseline: 3.9017x; 1.0102x over previous
#include <cuda_runtime.h>
#include <math.h>
#include <stdint.h>

#define CC 10

static const int BLOCK = 256;
static const int GRID  = 296;      // 2 blocks per SM
static const int WPB   = 8;
static const int NWARPS = GRID * WPB;

// Per-block partials: 0..9 sum p, 10..19 sum p^2, 20..29 sum v, 30 sum logsumexp
__device__ double g_partials[GRID][32];
__device__ unsigned int g_ticket = 0;   // reset by last block -> deterministic replays

// ---------------------------------------------------------------------------
__device__ __forceinline__ uint32_t smem_u32(const void* p) {
    uint32_t a;
    asm("{ .reg .u64 t; cvta.to.shared.u64 t, %1; cvt.u32.u64 %0, t; }"
        : "=r"(a) : "l"(p));
    return a;
}
__device__ __forceinline__ void cp16(uint32_t s, const void* g) {
    asm volatile("cp.async.cg.shared.global [%0], [%1], 16;" :: "r"(s), "l"(g));
}
#define CP_COMMIT() asm volatile("cp.async.commit_group;")
#define CP_WAIT1()  asm volatile("cp.async.wait_group 1;")

// ---------------------------------------------------------------------------
// Fused branchless digamma + trigamma (shift to x+6 + asymptotic series).
// ---------------------------------------------------------------------------
__device__ __forceinline__ void psi01(float x, float& dg, float& tg) {
    float s0 = 0.f, s1 = 0.f;
#pragma unroll
    for (int k = 0; k < 6; k++) {
        float r = __fdividef(1.f, x + (float)k);
        s0 += r;
        s1  = fmaf(r, r, s1);
    }
    float y  = x + 6.f;
    float r  = __fdividef(1.f, y);
    float r2 = r * r;
    dg = __logf(y) - 0.5f * r
       - r2 * (0.0833333333f - r2 * (0.0083333333f - r2 * 0.0039682540f))
       - s0;
    tg = r + 0.5f * r2
       + r * r2 * (0.1666666667f - r2 * (0.0333333333f - r2 * 0.0238095238f))
       + s1;
}

__device__ __forceinline__ void allred2_16(float& v1, float& v2) {
#pragma unroll
    for (int o = 8; o > 0; o >>= 1) {
        v1 += __shfl_xor_sync(0xffffffffu, v1, o);
        v2 += __shfl_xor_sync(0xffffffffu, v2, o);
    }
}
__device__ __forceinline__ float allred1_16(float v) {
#pragma unroll
    for (int o = 8; o > 0; o >>= 1) v += __shfl_xor_sync(0xffffffffu, v, o);
    return v;
}

// ---------------------------------------------------------------------------
// Single kernel: stats (cp.async double-buffered staging) + ticketed tail
// (partials reduction + Newton solve) in the last-arriving block.
// ---------------------------------------------------------------------------
__global__ __launch_bounds__(256) void ed_fused(const float* __restrict__ x,
                                                float* __restrict__ out, int n) {
    __shared__ float4 stage[WPB][2][160];

    const int lane = threadIdx.x & 31;
    const int w    = threadIdx.x >> 5;
    const int gw   = blockIdx.x * WPB + w;

    float ap [CC], ap2[CC], sv[CC];
    float sM = 0.f;
#pragma unroll
    for (int i = 0; i < CC; i++) { ap[i] = 0.f; ap2[i] = 0.f; sv[i] = 0.f; }

    const float4* __restrict__ x4 = reinterpret_cast<const float4*>(x);
    const int nT = n >> 6;

    const uint32_t sb0 = smem_u32(&stage[w][0][0]);
    const uint32_t sb1 = smem_u32(&stage[w][1][0]);

    int t = gw;
    if (t < nT) {
        const float4* src = x4 + (size_t)t * 160;
#pragma unroll
        for (int j = 0; j < 5; j++)
            cp16(sb0 + (uint32_t)(lane + j * 32) * 16u, src + lane + j * 32);
    }
    CP_COMMIT();

    int cur = 0;
    for (; t < nT; t += NWARPS) {
        const int t2 = t + NWARPS;
        const uint32_t sbn = cur ? sb0 : sb1;
        if (t2 < nT) {
            const float4* src = x4 + (size_t)t2 * 160;
#pragma unroll
            for (int j = 0; j < 5; j++)
                cp16(sbn + (uint32_t)(lane + j * 32) * 16u, src + lane + j * 32);
        }
        CP_COMMIT();
        CP_WAIT1();
        __syncwarp();

        const float4* b = &stage[w][cur][0];
        float4 q0 = b[lane * 5    ];
        float4 q1 = b[lane * 5 + 1];
        float4 q2 = b[lane * 5 + 2];
        float4 q3 = b[lane * 5 + 3];
        float4 q4 = b[lane * 5 + 4];

        float v0[CC] = { q0.x, q0.y, q0.z, q0.w, q1.x, q1.y, q1.z, q1.w, q2.x, q2.y };
        float v1[CC] = { q2.z, q2.w, q3.x, q3.y, q3.z, q3.w, q4.x, q4.y, q4.z, q4.w };

        float e0[CC], e1[CC];
#pragma unroll
        for (int i = 0; i < CC; i++) { e0[i] = __expf(v0[i]); e1[i] = __expf(v1[i]); }

        float s0 = ((e0[0]+e0[1]) + (e0[2]+e0[3])) + ((e0[4]+e0[5]) + (e0[6]+e0[7])) + (e0[8]+e0[9]);
        float s1 = ((e1[0]+e1[1]) + (e1[2]+e1[3])) + ((e1[4]+e1[5]) + (e1[6]+e1[7])) + (e1[8]+e1[9]);

        float inv0 = __fdividef(1.f, s0);
        float inv1 = __fdividef(1.f, s1);
        sM += __logf(s0);
        sM += __logf(s1);

#pragma unroll
        for (int i = 0; i < CC; i++) {
            float p0 = e0[i] * inv0;
            float p1 = e1[i] * inv1;
            ap [i] += p0 + p1;
            ap2[i]  = fmaf(p0, p0, ap2[i]);
            ap2[i]  = fmaf(p1, p1, ap2[i]);
            sv [i] += v0[i] + v1[i];
        }

        __syncwarp();
        cur ^= 1;
    }

    // tail rows (none for n % 64 == 0, kept for generality)
    for (int r0 = (nT << 6) + blockIdx.x * blockDim.x + threadIdx.x; r0 < n;
         r0 += gridDim.x * blockDim.x) {
        const float2* row = reinterpret_cast<const float2*>(x) + r0 * 5;
        float v[CC];
#pragma unroll
        for (int j = 0; j < 5; j++) { float2 t2 = row[j]; v[2*j] = t2.x; v[2*j+1] = t2.y; }
        float e[CC], s = 0.f;
#pragma unroll
        for (int i = 0; i < CC; i++) { e[i] = __expf(v[i]); s += e[i]; }
        float inv = __fdividef(1.f, s);
        sM += __logf(s);
#pragma unroll
        for (int i = 0; i < CC; i++) {
            float p = e[i] * inv;
            ap[i] += p; ap2[i] = fmaf(p, p, ap2[i]); sv[i] += v[i];
        }
    }

    // ---- block reduction: 31 stats -> double partials ----
#pragma unroll
    for (int i = 0; i < CC; i++) {
#pragma unroll
        for (int o = 16; o > 0; o >>= 1) {
            ap [i] += __shfl_down_sync(0xffffffffu, ap [i], o);
            ap2[i] += __shfl_down_sync(0xffffffffu, ap2[i], o);
            sv [i] += __shfl_down_sync(0xffffffffu, sv [i], o);
        }
    }
#pragma unroll
    for (int o = 16; o > 0; o >>= 1) sM += __shfl_down_sync(0xffffffffu, sM, o);

    __shared__ float sh[31][WPB];
    if (lane == 0) {
#pragma unroll
        for (int i = 0; i < CC; i++) {
            sh[i     ][w] = ap [i];
            sh[10 + i][w] = ap2[i];
            sh[20 + i][w] = sv [i];
        }
        sh[30][w] = sM;
    }
    __syncthreads();
    if (threadIdx.x < 31) {
        double s2 = 0.0;
#pragma unroll
        for (int w2 = 0; w2 < WPB; w2++) s2 += (double)sh[threadIdx.x][w2];
        g_partials[blockIdx.x][threadIdx.x] = s2;
    }

    // ---------------- ticketed tail: last block solves ----------------------
    __shared__ bool amLast;
    __threadfence();
    if (threadIdx.x == 0) {
        unsigned int tk = atomicAdd(&g_ticket, 1u);
        amLast = (tk == (unsigned int)(gridDim.x - 1));
    }
    __syncthreads();
    if (!amLast) return;

    if (threadIdx.x == 0) g_ticket = 0;   // reset for next graph replay

    // reduce 296x32 partials: stat = tid>>3, 8 threads per stat, 37 loads each
    __shared__ double st[32];
    {
        const int stat = threadIdx.x >> 3, j = threadIdx.x & 7;
        double s = 0.0;
#pragma unroll 4
        for (int b = j; b < GRID; b += 8) s += g_partials[b][stat];
        s += __shfl_down_sync(0xffffffffu, s, 4, 8);
        s += __shfl_down_sync(0xffffffffu, s, 2, 8);
        s += __shfl_down_sync(0xffffffffu, s, 1, 8);
        if (j == 0) st[stat] = s;
    }
    __syncthreads();

    if (threadIdx.x < 32) {
        const int  l   = threadIdx.x;
        const bool act = (l < CC);
        const double dn = (double)n;

        float m1  = act ? (float)(st[l]      / dn) : 0.f;
        float m2  = act ? (float)(st[10 + l] / dn) : 0.f;
        float lpa = act ? (float)((st[20 + l] - st[30]) / dn) : 0.f;

        float ratio = act ? (m1 - m2) / (m2 - m1 * m1) : 0.f;
        float rmean = allred1_16(ratio) * 0.1f;
        float a     = act ? m1 * rmean : 0.f;
        float asum  = allred1_16(a);
        if (!act) { a = 1.0f; asum = 20.0f; }

#pragma unroll 1
        for (int k = 0; k < 10; k++) {
            float dga, tga, dgs, tgs;
            psi01(a,    dga, tga);
            psi01(asum, dgs, tgs);
            float g    = dgs - dga + lpa;
            float qinv = __fdividef(-1.f, tga);
            float num  = act ? g * qinv : 0.f;
            float qs   = act ? qinv     : 0.f;
            allred2_16(num, qs);
            float zinv = __fdividef(1.f, tgs);
            float b    = num / (zinv + qs);
            a    = act ? a - (g - b) * qinv : 1.0f;
            asum = act ? asum - (num - b * qs) : 20.0f;
        }
        if (act) out[l] = a;
    }
}

// ---------------------------------------------------------------------------
extern "C" void kernel_launch(void* const* d_in, const int* in_sizes, int n_in,
                              void* d_out, int out_size) {
    const float* x = (const float*)d_in[0];
    const int n = in_sizes[0] / CC;   // 2,000,000 rows
    ed_fused<<<GRID, BLOCK>>>(x, (float*)d_out, n);
}